// round 8
// baseline (speedup 1.0000x reference)
#include <cuda_runtime.h>
#include <math.h>

#define GRIDW 64
#define PADW  67              // 1 low pad + 2 high pad (tent taps reach x0+2)
#define CIN   80
#define HID   64
#define SPR   96
#define NRAY  4096
#define NPTS  (NRAY*SPR)
#define PLANE_TEXELS (PADW*PADW)
#define PLANE_FLOATS (PLANE_TEXELS*HID)

typedef unsigned long long ull;

// W1-projected planes, zero-padded border: [p][y+1][x+1][j]
__device__ float g_PL[3*PLANE_FLOATS];
// per-point scratch: [point][8] = {rgb0,rgb1,rgb2,sigma, n0,n1,n2,pad}
__device__ float g_scr[NPTS*8];
// per-ray packed params: [ray*2] = (ro+tn*rd, tn), [ray*2+1] = (span*rd, span)
__device__ float4 g_rayp[NRAY*2];
// transposed W2: W2T[c][j] = W2[j][c]
__device__ float g_W2T[4*64];

__device__ __forceinline__ float sum32(float v) {
    #pragma unroll
    for (int off = 16; off; off >>= 1)
        v += __shfl_xor_sync(0xffffffffu, v, off);
    return v;
}

// ---- packed f32x2 helpers -------------------------------------------------
struct P2 { ull a, b; };   // 4 floats as 2 packed f32x2

// D += {w,w} * v   (4 channels)
__device__ __forceinline__ void accp(P2& D, float w, const ulonglong2 v) {
    ull wp;
    asm("mov.b64 %0, {%1, %1};" : "=l"(wp) : "f"(w));
    asm("fma.rn.f32x2 %0, %1, %2, %0;" : "+l"(D.a) : "l"(wp), "l"(v.x));
    asm("fma.rn.f32x2 %0, %1, %2, %0;" : "+l"(D.b) : "l"(wp), "l"(v.y));
}
__device__ __forceinline__ void addp(P2& D, const P2 S) {
    asm("add.rn.f32x2 %0, %1, %0;" : "+l"(D.a) : "l"(S.a));
    asm("add.rn.f32x2 %0, %1, %0;" : "+l"(D.b) : "l"(S.b));
}
__device__ __forceinline__ void unpack4(const P2 S, float* f) {
    asm("mov.b64 {%0, %1}, %2;" : "=f"(f[0]), "=f"(f[1]) : "l"(S.a));
    asm("mov.b64 {%0, %1}, %2;" : "=f"(f[2]), "=f"(f[3]) : "l"(S.b));
}

// ---------------------------------------------------------------------------
// Kernel 0a: per-ray box intersection + packed ray params
// ---------------------------------------------------------------------------
__global__ void ray_setup(const float* __restrict__ ro_all,
                          const float* __restrict__ rd_all) {
    const int r = blockIdx.x * blockDim.x + threadIdx.x;
    if (r >= NRAY) return;
    const float ro0 = ro_all[r*3+0], ro1 = ro_all[r*3+1], ro2 = ro_all[r*3+2];
    const float rd0 = rd_all[r*3+0], rd1 = rd_all[r*3+1], rd2 = rd_all[r*3+2];
    float tn = 0.f, tf = 3.402823e38f;
    const float o[3] = {ro0, ro1, ro2};
    const float d[3] = {rd0, rd1, rd2};
    #pragma unroll
    for (int i = 0; i < 3; i++) {
        float srd = (fabsf(d[i]) < 1e-9f) ? 1e-9f : d[i];
        float ta = (-0.6f - o[i]) / srd;
        float tb = ( 0.6f - o[i]) / srd;
        tn = fmaxf(tn, fminf(ta, tb));
        tf = fminf(tf, fmaxf(ta, tb));
    }
    const float span = fmaxf(tf - tn, 0.f);
    g_rayp[r*2]   = make_float4(fmaf(tn, rd0, ro0), fmaf(tn, rd1, ro1), fmaf(tn, rd2, ro2), tn);
    g_rayp[r*2+1] = make_float4(span*rd0, span*rd1, span*rd2, span);
}

// ---------------------------------------------------------------------------
// Kernel 0b: zero pad border texels + build W2T
// ---------------------------------------------------------------------------
__global__ void zero_border(const float* __restrict__ W2) {
    const int i = blockIdx.x * blockDim.x + threadIdx.x;
    if (i < 256) {
        const int c = i >> 6, j = i & 63;
        g_W2T[c*64 + j] = W2[j*4 + c];
    }
    if (i >= 3*PLANE_TEXELS*16) return;
    const int tex = i >> 4;
    const int q   = i & 15;
    const int t   = tex % PLANE_TEXELS;
    const int y   = t / PADW;
    const int x   = t - y*PADW;
    if (x == 0 || x >= PADW-2 || y == 0 || y >= PADW-2) {
        float4 z; z.x = z.y = z.z = z.w = 0.f;
        *reinterpret_cast<float4*>(&g_PL[(size_t)tex*HID + q*4]) = z;
    }
}

// ---------------------------------------------------------------------------
// Kernel 1: PL[p][y+1][x+1][j] = sum_c planes[p][c][y][x] * W1[p*80+c][j]
// packed f32x2 inner loop: 4 FFMA2 per channel instead of 8 FFMA.
// ---------------------------------------------------------------------------
__global__ __launch_bounds__(512) void project_planes(const float* __restrict__ planes,
                                                      const float* __restrict__ W1) {
    const int blk = blockIdx.x;
    const int p = blk >> 6;
    const int y = blk & 63;
    __shared__ float feats[CIN][GRIDW];
    __shared__ float w1s[CIN][HID];
    const int tid = threadIdx.x;
    for (int i = tid; i < CIN*GRIDW; i += 512) {
        int c = i >> 6, x = i & 63;
        feats[c][x] = planes[(((p*CIN + c)*GRIDW) + y)*GRIDW + x];
        w1s[c][x]   = W1[(p*CIN + c)*HID + x];
    }
    __syncthreads();
    const int x  = tid >> 3;
    const int jg = (tid & 7) * 8;
    P2 acc0 = {0,0}, acc1 = {0,0};
    #pragma unroll 8
    for (int c = 0; c < CIN; c++) {
        const float f = feats[c][x];
        const ulonglong2 w0 = *reinterpret_cast<const ulonglong2*>(&w1s[c][jg]);
        const ulonglong2 w1 = *reinterpret_cast<const ulonglong2*>(&w1s[c][jg+4]);
        accp(acc0, f, w0);
        accp(acc1, f, w1);
    }
    ull* dst = reinterpret_cast<ull*>(&g_PL[((size_t)p*PLANE_TEXELS + (size_t)(y+1)*PADW + (x+1))*HID + jg]);
    dst[0] = acc0.a; dst[1] = acc0.b; dst[2] = acc1.a; dst[3] = acc1.b;
}

// ---------------------------------------------------------------------------
// axis helper: base floor index (padded), base frac w, tent weights q[3]
// ---------------------------------------------------------------------------
struct Ax { int i1; float w; float q0, q1, q2; };
__device__ __forceinline__ Ax mkax(float p) {
    const float SCL32 = (2.0f/1.2f) * 32.f;
    const float f  = fmaf(p, SCL32, 31.5f);
    const float fl = floorf(f);
    const float qc = fminf(fmaxf(p + 0.01f, -0.6f), 0.6f);
    const float fq = fmaf(qc, SCL32, 31.5f);
    const float t  = fq - fl;                 // in [0, 2)
    Ax a;
    a.i1 = (int)fl + 1;
    a.w  = f - fl;
    a.q0 = fmaxf(1.f - t, 0.f);
    a.q1 = fmaxf(1.f - fabsf(t - 1.f), 0.f);
    a.q2 = fmaxf(t - 1.f, 0.f);
    return a;
}

// One plane: 8-texel L-footprint, 4 channels/lane, packed f32x2.
// Base partial -> temp T, then added into Bb and Bw. FD-u -> Bu; FD-v -> Bv.
__device__ __forceinline__ void do_plane(const float* __restrict__ tp,
        const Ax U, const Ax V,
        P2& Bb, P2& Bw, P2& Bu, P2& Bv) {
    const float bx0 = 1.f - U.w, bx1 = U.w;
    const float by0 = 1.f - V.w, by1 = V.w;
    P2 T = {0,0};
    #define TEXEL(i, j) (*reinterpret_cast<const ulonglong2*>(tp + ((j)*PADW + (i))*HID))
    {   const ulonglong2 v = TEXEL(0,0);
        accp(T,  bx0*by0,  v);
        accp(Bu, U.q0*by0, v);
        accp(Bv, bx0*V.q0, v);
    }
    {   const ulonglong2 v = TEXEL(1,0);
        accp(T,  bx1*by0,  v);
        accp(Bu, U.q1*by0, v);
        accp(Bv, bx1*V.q0, v);
    }
    {   const ulonglong2 v = TEXEL(2,0);
        accp(Bu, U.q2*by0, v);
    }
    {   const ulonglong2 v = TEXEL(0,1);
        accp(T,  bx0*by1,  v);
        accp(Bu, U.q0*by1, v);
        accp(Bv, bx0*V.q1, v);
    }
    {   const ulonglong2 v = TEXEL(1,1);
        accp(T,  bx1*by1,  v);
        accp(Bu, U.q1*by1, v);
        accp(Bv, bx1*V.q1, v);
    }
    {   const ulonglong2 v = TEXEL(2,1);
        accp(Bu, U.q2*by1, v);
    }
    {   const ulonglong2 v = TEXEL(0,2);
        accp(Bv, bx0*V.q2, v);
    }
    {   const ulonglong2 v = TEXEL(1,2);
        accp(Bv, bx1*V.q2, v);
    }
    #undef TEXEL
    addp(Bb, T);
    addp(Bw, T);
}

// ---------------------------------------------------------------------------
// Kernel 2: 2 points per warp, 16 lanes/point, 4 channels/lane.
// ---------------------------------------------------------------------------
__global__ __launch_bounds__(256, 4) void point_kernel(
        const float* __restrict__ b1,
        const float* __restrict__ b2,
        float* __restrict__ grad_out) {
    const int lane = threadIdx.x & 31;
    const int sub  = lane & 15;
    const int point = blockIdx.x * 16 + (threadIdx.x >> 5) * 2 + (lane >> 4);
    const int ray   = point / SPR;
    const int s     = point - ray * SPR;

    const float4 A4 = g_rayp[ray*2];
    const float4 B4 = g_rayp[ray*2+1];
    const float frac = ((float)s + 0.5f) * (1.0f/96.0f);
    const float px = fmaf(B4.x, frac, A4.x);
    const float py = fmaf(B4.y, frac, A4.y);
    const float pz = fmaf(B4.z, frac, A4.z);

    const Ax X = mkax(px);
    const Ax Y = mkax(py);
    const Ax Z = mkax(pz);

    P2 Hb = {0,0}, Hx = {0,0}, Hy = {0,0}, Hz = {0,0};

    const float* PLL = g_PL + sub*4;
    // plane0 (x,y): base->Hb,Hz ; xFD->Hx ; yFD->Hy
    do_plane(PLL + ((size_t)0*PLANE_TEXELS + (size_t)Y.i1*PADW + X.i1)*HID,
             X, Y, Hb, Hz, Hx, Hy);
    // plane1 (x,z): base->Hb,Hy ; xFD->Hx ; zFD->Hz
    do_plane(PLL + ((size_t)1*PLANE_TEXELS + (size_t)Z.i1*PADW + X.i1)*HID,
             X, Z, Hb, Hy, Hx, Hz);
    // plane2 (y,z): base->Hb,Hx ; yFD->Hy ; zFD->Hz
    do_plane(PLL + ((size_t)2*PLANE_TEXELS + (size_t)Z.i1*PADW + Y.i1)*HID,
             Y, Z, Hb, Hx, Hy, Hz);

    // epilogue weights: b1 (contiguous) + transposed W2 columns (contiguous)
    const float4 b1v = *reinterpret_cast<const float4*>(b1 + sub*4);
    const float4 wc0 = *reinterpret_cast<const float4*>(&g_W2T[0*64 + sub*4]);
    const float4 wc1 = *reinterpret_cast<const float4*>(&g_W2T[1*64 + sub*4]);
    const float4 wc2 = *reinterpret_cast<const float4*>(&g_W2T[2*64 + sub*4]);
    const float4 wc3 = *reinterpret_cast<const float4*>(&g_W2T[3*64 + sub*4]);

    float HbV[4], HxV[4], HyV[4], HzV[4];
    unpack4(Hb, HbV); unpack4(Hx, HxV); unpack4(Hy, HyV); unpack4(Hz, HzV);

    const float hb0 = fmaxf(HbV[0] + b1v.x, 0.f);
    const float hb1 = fmaxf(HbV[1] + b1v.y, 0.f);
    const float hb2 = fmaxf(HbV[2] + b1v.z, 0.f);
    const float hb3 = fmaxf(HbV[3] + b1v.w, 0.f);
    const float hx0 = fmaxf(HxV[0] + b1v.x, 0.f);
    const float hx1 = fmaxf(HxV[1] + b1v.y, 0.f);
    const float hx2 = fmaxf(HxV[2] + b1v.z, 0.f);
    const float hx3 = fmaxf(HxV[3] + b1v.w, 0.f);
    const float hy0 = fmaxf(HyV[0] + b1v.x, 0.f);
    const float hy1 = fmaxf(HyV[1] + b1v.y, 0.f);
    const float hy2 = fmaxf(HyV[2] + b1v.z, 0.f);
    const float hy3 = fmaxf(HyV[3] + b1v.w, 0.f);
    const float hz0 = fmaxf(HzV[0] + b1v.x, 0.f);
    const float hz1 = fmaxf(HzV[1] + b1v.y, 0.f);
    const float hz2 = fmaxf(HzV[2] + b1v.z, 0.f);
    const float hz3 = fmaxf(HzV[3] + b1v.w, 0.f);

    const float v0 = fmaf(hb0,wc0.x, fmaf(hb1,wc0.y, fmaf(hb2,wc0.z, hb3*wc0.w)));
    const float v1 = fmaf(hb0,wc1.x, fmaf(hb1,wc1.y, fmaf(hb2,wc1.z, hb3*wc1.w)));
    const float v2 = fmaf(hb0,wc2.x, fmaf(hb1,wc2.y, fmaf(hb2,wc2.z, hb3*wc2.w)));
    const float v3 = fmaf(hb0,wc3.x, fmaf(hb1,wc3.y, fmaf(hb2,wc3.z, hb3*wc3.w)));
    const float vx = fmaf(hx0,wc0.x, fmaf(hx1,wc0.y, fmaf(hx2,wc0.z, hx3*wc0.w)));
    const float vy = fmaf(hy0,wc0.x, fmaf(hy1,wc0.y, fmaf(hy2,wc0.z, hy3*wc0.w)));
    const float vz = fmaf(hz0,wc0.x, fmaf(hz1,wc0.y, fmaf(hz2,wc0.z, hz3*wc0.w)));

    // --- packed multi-value reduction over 16 lanes (values: v0..v3,vx,vy,vz,0)
    const bool lo1 = (lane & 1) == 0;
    float s0 = lo1 ? vx : v0;
    float s1 = lo1 ? vy : v1;
    float s2 = lo1 ? vz : v2;
    float s3 = lo1 ? 0.f : v3;
    s0 = __shfl_xor_sync(0xffffffffu, s0, 1);
    s1 = __shfl_xor_sync(0xffffffffu, s1, 1);
    s2 = __shfl_xor_sync(0xffffffffu, s2, 1);
    s3 = __shfl_xor_sync(0xffffffffu, s3, 1);
    const float a0 = (lo1 ? v0 : vx) + s0;
    const float a1 = (lo1 ? v1 : vy) + s1;
    const float a2 = (lo1 ? v2 : vz) + s2;
    const float a3 = (lo1 ? v3 : 0.f) + s3;
    const bool lo2 = ((lane >> 1) & 1) == 0;
    float u0 = lo2 ? a2 : a0;
    float u1 = lo2 ? a3 : a1;
    u0 = __shfl_xor_sync(0xffffffffu, u0, 2);
    u1 = __shfl_xor_sync(0xffffffffu, u1, 2);
    const float c0 = (lo2 ? a0 : a2) + u0;
    const float c1 = (lo2 ? a1 : a3) + u1;
    const bool lo3 = ((lane >> 2) & 1) == 0;
    float w = lo3 ? c1 : c0;
    w = __shfl_xor_sync(0xffffffffu, w, 4);
    float dsum = (lo3 ? c0 : c1) + w;
    dsum += __shfl_xor_sync(0xffffffffu, dsum, 8);
    // value j lives at half-lane L(j) = bitrev3(j): {0,4,2,6,1,5,3,7}
    const int hb16 = lane & 16;
    const float4 b2v = *reinterpret_cast<const float4*>(b2);
    const float sdf_base = __shfl_sync(0xffffffffu, dsum, hb16 + 0) + b2v.x;
    const float rgb1v    = __shfl_sync(0xffffffffu, dsum, hb16 + 4) + b2v.y;
    const float rgb2v    = __shfl_sync(0xffffffffu, dsum, hb16 + 2) + b2v.z;
    const float rgb3v    = __shfl_sync(0xffffffffu, dsum, hb16 + 6) + b2v.w;
    const float sdfx     = __shfl_sync(0xffffffffu, dsum, hb16 + 1) + b2v.x;
    const float sdfy     = __shfl_sync(0xffffffffu, dsum, hb16 + 5) + b2v.x;
    const float sdfz     = __shfl_sync(0xffffffffu, dsum, hb16 + 3) + b2v.x;

    if (sub == 0) {
        const float g0 = (sdfx - sdf_base) * 100.f;
        const float g1 = (sdfy - sdf_base) * 100.f;
        const float g2 = (sdfz - sdf_base) * 100.f;
        grad_out[point*3 + 0] = g0;
        grad_out[point*3 + 1] = g1;
        grad_out[point*3 + 2] = g2;
        const float gn  = sqrtf(g0*g0 + g1*g1 + g2*g2);
        const float inv = 1.f / (gn + 1e-8f);
        const float shifted = sdf_base + sqrtf(px*px + py*py + pz*pz) - 0.5f;
        const float xs = -shifted * 80.f;
        const float sigma = fmaxf(xs, 0.f) + log1pf(expf(-fabsf(xs)));
        const float r1 = 1.002f / (1.f + expf(-rgb1v)) - 0.001f;
        const float r2 = 1.002f / (1.f + expf(-rgb2v)) - 0.001f;
        const float r3 = 1.002f / (1.f + expf(-rgb3v)) - 0.001f;
        float4 A; A.x = r1; A.y = r2; A.z = r3; A.w = sigma;
        float4 B; B.x = g0*inv; B.y = g1*inv; B.z = g2*inv; B.w = 0.f;
        *reinterpret_cast<float4*>(&g_scr[point*8    ]) = A;
        *reinterpret_cast<float4*>(&g_scr[point*8 + 4]) = B;
    }
}

// ---------------------------------------------------------------------------
// Kernel 3: warp-per-ray compositing via multiplicative prefix scan.
// ---------------------------------------------------------------------------
__global__ void composite(float* __restrict__ out) {
    const int lane = threadIdx.x & 31;
    const int r = blockIdx.x * 8 + (threadIdx.x >> 5);

    const float tn   = g_rayp[r*2].w;
    const float span = g_rayp[r*2+1].w;
    const float delta = span * (1.0f/96.0f);

    float rgb0=0.f, rgb1=0.f, rgb2=0.f, dep=0.f, ws=0.f, n0=0.f, n1=0.f, n2=0.f;
    float Tpre = 1.f;
    #pragma unroll
    for (int k = 0; k < 3; k++) {
        const int s = k*32 + lane;
        const float4 A = *reinterpret_cast<const float4*>(&g_scr[(size_t)(r*SPR + s)*8]);
        const float4 B = *reinterpret_cast<const float4*>(&g_scr[(size_t)(r*SPR + s)*8 + 4]);
        const float e = expf(-A.w * delta);
        const float m = e + 1e-10f;
        const float alpha = 1.f - e;
        float incl = m;
        #pragma unroll
        for (int off = 1; off < 32; off <<= 1) {
            float t = __shfl_up_sync(0xffffffffu, incl, off);
            if (lane >= off) incl *= t;
        }
        float excl = __shfl_up_sync(0xffffffffu, incl, 1);
        if (lane == 0) excl = 1.f;
        const float tot = __shfl_sync(0xffffffffu, incl, 31);
        const float T = Tpre * excl;
        const float w = alpha * T;
        rgb0 = fmaf(w, A.x, rgb0);
        rgb1 = fmaf(w, A.y, rgb1);
        rgb2 = fmaf(w, A.z, rgb2);
        dep  = fmaf(w, tn + span * (((float)s + 0.5f) * (1.0f/96.0f)), dep);
        ws  += w;
        n0 = fmaf(w, B.x, n0);
        n1 = fmaf(w, B.y, n1);
        n2 = fmaf(w, B.z, n2);
        Tpre *= tot;
    }
    rgb0 = sum32(rgb0);
    rgb1 = sum32(rgb1);
    rgb2 = sum32(rgb2);
    dep  = sum32(dep);
    ws   = sum32(ws);
    n0   = sum32(n0);
    n1   = sum32(n1);
    n2   = sum32(n2);

    if (lane == 0) {
        const float bg = 1.f - ws;
        const float nn  = sqrtf(n0*n0 + n1*n1 + n2*n2);
        const float inv = 1.f / (nn + 1e-8f);
        out[r]         = rgb0 + bg;
        out[ 4096 + r] = rgb1 + bg;
        out[ 8192 + r] = rgb2 + bg;
        out[12288 + r] = dep;
        out[16384 + r] = ws;
        out[20480 + r] = ((n0*inv) + 1.f) * 0.5f * ws;
        out[24576 + r] = ((n1*inv) + 1.f) * 0.5f * ws;
        out[28672 + r] = ((n2*inv) + 1.f) * 0.5f * ws;
    }
}

// ---------------------------------------------------------------------------
extern "C" void kernel_launch(void* const* d_in, const int* in_sizes, int n_in,
                              void* d_out, int out_size) {
    const float* planes = (const float*)d_in[0];
    const float* ro     = (const float*)d_in[1];
    const float* rd     = (const float*)d_in[2];
    const float* W1     = (const float*)d_in[3];
    const float* b1     = (const float*)d_in[4];
    const float* W2     = (const float*)d_in[5];
    const float* b2     = (const float*)d_in[6];
    float* out = (float*)d_out;

    ray_setup<<<(NRAY + 255)/256, 256>>>(ro, rd);
    zero_border<<<(3*PLANE_TEXELS*16 + 255)/256, 256>>>(W2);
    project_planes<<<3*GRIDW, 512>>>(planes, W1);
    point_kernel<<<NPTS/16, 256>>>(b1, b2, out + 32768);
    composite<<<NRAY/8, 256>>>(out);
}

// round 9
// speedup vs baseline: 1.6023x; 1.6023x over previous
#include <cuda_runtime.h>
#include <math.h>

#define GRIDW 64
#define PADW  67              // 1 low pad + 2 high pad (tent taps reach x0+2)
#define CIN   80
#define HID   64
#define SPR   96
#define NRAY  4096
#define NPTS  (NRAY*SPR)
#define PLANE_TEXELS (PADW*PADW)
#define PLANE_FLOATS (PLANE_TEXELS*HID)

// W1-projected planes, zero-padded border: [p][y+1][x+1][j]
__device__ float g_PL[3*PLANE_FLOATS];
// per-point scratch: [point][8] = {rgb0,rgb1,rgb2,sigma, n0,n1,n2,pad}
__device__ float g_scr[NPTS*8];
// per-ray packed params: [ray*2] = (ro+tn*rd, tn), [ray*2+1] = (span*rd, span)
__device__ float4 g_rayp[NRAY*2];
// transposed W2: W2T[c][j] = W2[j][c]
__device__ float g_W2T[4*64];

__device__ __forceinline__ float sum32(float v) {
    #pragma unroll
    for (int off = 16; off; off >>= 1)
        v += __shfl_xor_sync(0xffffffffu, v, off);
    return v;
}

// ---------------------------------------------------------------------------
// Kernel 0: zero pad border texels + build W2T + per-ray box intersection
// ---------------------------------------------------------------------------
__global__ void setup_kernel(const float* __restrict__ W2,
                             const float* __restrict__ ro_all,
                             const float* __restrict__ rd_all) {
    const int i = blockIdx.x * blockDim.x + threadIdx.x;
    if (i < 256) {
        const int c = i >> 6, j = i & 63;
        g_W2T[c*64 + j] = W2[j*4 + c];
    }
    if (i < NRAY) {
        const int r = i;
        const float ro0 = ro_all[r*3+0], ro1 = ro_all[r*3+1], ro2 = ro_all[r*3+2];
        const float rd0 = rd_all[r*3+0], rd1 = rd_all[r*3+1], rd2 = rd_all[r*3+2];
        float tn = 0.f, tf = 3.402823e38f;
        const float o[3] = {ro0, ro1, ro2};
        const float d[3] = {rd0, rd1, rd2};
        #pragma unroll
        for (int k = 0; k < 3; k++) {
            float srd = (fabsf(d[k]) < 1e-9f) ? 1e-9f : d[k];
            float ta = (-0.6f - o[k]) / srd;
            float tb = ( 0.6f - o[k]) / srd;
            tn = fmaxf(tn, fminf(ta, tb));
            tf = fminf(tf, fmaxf(ta, tb));
        }
        const float span = fmaxf(tf - tn, 0.f);
        g_rayp[r*2]   = make_float4(fmaf(tn, rd0, ro0), fmaf(tn, rd1, ro1), fmaf(tn, rd2, ro2), tn);
        g_rayp[r*2+1] = make_float4(span*rd0, span*rd1, span*rd2, span);
    }
    if (i >= 3*PLANE_TEXELS*16) return;
    const int tex = i >> 4;
    const int q   = i & 15;
    const int t   = tex % PLANE_TEXELS;
    const int y   = t / PADW;
    const int x   = t - y*PADW;
    if (x == 0 || x >= PADW-2 || y == 0 || y >= PADW-2) {
        float4 z; z.x = z.y = z.z = z.w = 0.f;
        *reinterpret_cast<float4*>(&g_PL[(size_t)tex*HID + q*4]) = z;
    }
}

// ---------------------------------------------------------------------------
// Kernel 1: PL[p][y+1][x+1][j] = sum_c planes[p][c][y][x] * W1[p*80+c][j]
// ---------------------------------------------------------------------------
__global__ __launch_bounds__(512) void project_planes(const float* __restrict__ planes,
                                                      const float* __restrict__ W1) {
    const int blk = blockIdx.x;
    const int p = blk >> 6;
    const int y = blk & 63;
    __shared__ float feats[CIN][GRIDW];
    __shared__ float w1s[CIN][HID];
    const int tid = threadIdx.x;
    for (int i = tid; i < CIN*GRIDW; i += 512) {
        int c = i >> 6, x = i & 63;
        feats[c][x] = planes[(((p*CIN + c)*GRIDW) + y)*GRIDW + x];
        w1s[c][x]   = W1[(p*CIN + c)*HID + x];
    }
    __syncthreads();
    const int x  = tid >> 3;
    const int jg = (tid & 7) * 8;
    float acc[8];
    #pragma unroll
    for (int k = 0; k < 8; k++) acc[k] = 0.f;
    #pragma unroll 8
    for (int c = 0; c < CIN; c++) {
        const float f = feats[c][x];
        const float4 w0 = *reinterpret_cast<const float4*>(&w1s[c][jg]);
        const float4 w1 = *reinterpret_cast<const float4*>(&w1s[c][jg+4]);
        acc[0] = fmaf(f, w0.x, acc[0]);
        acc[1] = fmaf(f, w0.y, acc[1]);
        acc[2] = fmaf(f, w0.z, acc[2]);
        acc[3] = fmaf(f, w0.w, acc[3]);
        acc[4] = fmaf(f, w1.x, acc[4]);
        acc[5] = fmaf(f, w1.y, acc[5]);
        acc[6] = fmaf(f, w1.z, acc[6]);
        acc[7] = fmaf(f, w1.w, acc[7]);
    }
    float* dst = &g_PL[((size_t)p*PLANE_TEXELS + (size_t)(y+1)*PADW + (x+1))*HID + jg];
    float4 v0; v0.x=acc[0]; v0.y=acc[1]; v0.z=acc[2]; v0.w=acc[3];
    float4 v1; v1.x=acc[4]; v1.y=acc[5]; v1.z=acc[6]; v1.w=acc[7];
    *reinterpret_cast<float4*>(dst)     = v0;
    *reinterpret_cast<float4*>(dst + 4) = v1;
}

// ---------------------------------------------------------------------------
// axis helper: base floor index (padded), base frac w, tent weights q[3]
// ---------------------------------------------------------------------------
struct Ax { int i1; float w; float q0, q1, q2; };
__device__ __forceinline__ Ax mkax(float p) {
    const float SCL32 = (2.0f/1.2f) * 32.f;
    const float f  = fmaf(p, SCL32, 31.5f);
    const float fl = floorf(f);
    const float qc = fminf(fmaxf(p + 0.01f, -0.6f), 0.6f);
    const float fq = fmaf(qc, SCL32, 31.5f);
    const float t  = fq - fl;                 // in [0, 2)
    Ax a;
    a.i1 = (int)fl + 1;
    a.w  = f - fl;
    a.q0 = fmaxf(1.f - t, 0.f);
    a.q1 = fmaxf(1.f - fabsf(t - 1.f), 0.f);
    a.q2 = fmaxf(t - 1.f, 0.f);
    return a;
}

#define ACC4(D, W, V) \
    D.x = fmaf((W), (V).x, D.x); D.y = fmaf((W), (V).y, D.y); \
    D.z = fmaf((W), (V).z, D.z); D.w = fmaf((W), (V).w, D.w);

// One plane: 8-texel L-footprint, 4 channels/lane.
// Base partial -> temp T, added into Bb and Bw at the end. FD-u -> Bu; FD-v -> Bv.
__device__ __forceinline__ void do_plane(const float* __restrict__ tp,
        const Ax U, const Ax V,
        float4& Bb, float4& Bw, float4& Bu, float4& Bv) {
    const float bx0 = 1.f - U.w, bx1 = U.w;
    const float by0 = 1.f - V.w, by1 = V.w;
    float4 T = {0.f, 0.f, 0.f, 0.f};
    #define TEXEL(i, j) (*reinterpret_cast<const float4*>(tp + ((j)*PADW + (i))*HID))
    {   const float4 v = TEXEL(0,0);
        const float wb = bx0*by0, wu = U.q0*by0, wv = bx0*V.q0;
        ACC4(T, wb, v) ACC4(Bu, wu, v) ACC4(Bv, wv, v)
    }
    {   const float4 v = TEXEL(1,0);
        const float wb = bx1*by0, wu = U.q1*by0, wv = bx1*V.q0;
        ACC4(T, wb, v) ACC4(Bu, wu, v) ACC4(Bv, wv, v)
    }
    {   const float4 v = TEXEL(2,0);
        const float wu = U.q2*by0;
        ACC4(Bu, wu, v)
    }
    {   const float4 v = TEXEL(0,1);
        const float wb = bx0*by1, wu = U.q0*by1, wv = bx0*V.q1;
        ACC4(T, wb, v) ACC4(Bu, wu, v) ACC4(Bv, wv, v)
    }
    {   const float4 v = TEXEL(1,1);
        const float wb = bx1*by1, wu = U.q1*by1, wv = bx1*V.q1;
        ACC4(T, wb, v) ACC4(Bu, wu, v) ACC4(Bv, wv, v)
    }
    {   const float4 v = TEXEL(2,1);
        const float wu = U.q2*by1;
        ACC4(Bu, wu, v)
    }
    {   const float4 v = TEXEL(0,2);
        const float wv = bx0*V.q2;
        ACC4(Bv, wv, v)
    }
    {   const float4 v = TEXEL(1,2);
        const float wv = bx1*V.q2;
        ACC4(Bv, wv, v)
    }
    #undef TEXEL
    Bb.x += T.x; Bb.y += T.y; Bb.z += T.z; Bb.w += T.w;
    Bw.x += T.x; Bw.y += T.y; Bw.z += T.z; Bw.w += T.w;
}

// ---------------------------------------------------------------------------
// Kernel 2: 2 points per warp, 16 lanes/point, 4 channels/lane.
// ---------------------------------------------------------------------------
__global__ __launch_bounds__(256, 4) void point_kernel(
        const float* __restrict__ b1,
        const float* __restrict__ b2,
        float* __restrict__ grad_out) {
    const int lane = threadIdx.x & 31;
    const int sub  = lane & 15;
    const int point = blockIdx.x * 16 + (threadIdx.x >> 5) * 2 + (lane >> 4);
    const int ray   = point / SPR;
    const int s     = point - ray * SPR;

    const float4 A4 = g_rayp[ray*2];
    const float4 B4 = g_rayp[ray*2+1];
    const float frac = ((float)s + 0.5f) * (1.0f/96.0f);
    const float px = fmaf(B4.x, frac, A4.x);
    const float py = fmaf(B4.y, frac, A4.y);
    const float pz = fmaf(B4.z, frac, A4.z);

    const Ax X = mkax(px);
    const Ax Y = mkax(py);
    const Ax Z = mkax(pz);

    float4 Hb={0,0,0,0}, Hx={0,0,0,0}, Hy={0,0,0,0}, Hz={0,0,0,0};

    const float* PLL = g_PL + sub*4;
    // plane0 (x,y): base->Hb,Hz ; xFD->Hx ; yFD->Hy
    do_plane(PLL + ((size_t)0*PLANE_TEXELS + (size_t)Y.i1*PADW + X.i1)*HID,
             X, Y, Hb, Hz, Hx, Hy);
    // plane1 (x,z): base->Hb,Hy ; xFD->Hx ; zFD->Hz
    do_plane(PLL + ((size_t)1*PLANE_TEXELS + (size_t)Z.i1*PADW + X.i1)*HID,
             X, Z, Hb, Hy, Hx, Hz);
    // plane2 (y,z): base->Hb,Hx ; yFD->Hy ; zFD->Hz
    do_plane(PLL + ((size_t)2*PLANE_TEXELS + (size_t)Z.i1*PADW + Y.i1)*HID,
             Y, Z, Hb, Hx, Hy, Hz);

    // epilogue weights: b1 (contiguous) + transposed W2 columns (contiguous)
    const float4 b1v = *reinterpret_cast<const float4*>(b1 + sub*4);
    const float4 wc0 = *reinterpret_cast<const float4*>(&g_W2T[0*64 + sub*4]);
    const float4 wc1 = *reinterpret_cast<const float4*>(&g_W2T[1*64 + sub*4]);
    const float4 wc2 = *reinterpret_cast<const float4*>(&g_W2T[2*64 + sub*4]);
    const float4 wc3 = *reinterpret_cast<const float4*>(&g_W2T[3*64 + sub*4]);

    const float hb0 = fmaxf(Hb.x + b1v.x, 0.f);
    const float hb1 = fmaxf(Hb.y + b1v.y, 0.f);
    const float hb2 = fmaxf(Hb.z + b1v.z, 0.f);
    const float hb3 = fmaxf(Hb.w + b1v.w, 0.f);
    const float hx0 = fmaxf(Hx.x + b1v.x, 0.f);
    const float hx1 = fmaxf(Hx.y + b1v.y, 0.f);
    const float hx2 = fmaxf(Hx.z + b1v.z, 0.f);
    const float hx3 = fmaxf(Hx.w + b1v.w, 0.f);
    const float hy0 = fmaxf(Hy.x + b1v.x, 0.f);
    const float hy1 = fmaxf(Hy.y + b1v.y, 0.f);
    const float hy2 = fmaxf(Hy.z + b1v.z, 0.f);
    const float hy3 = fmaxf(Hy.w + b1v.w, 0.f);
    const float hz0 = fmaxf(Hz.x + b1v.x, 0.f);
    const float hz1 = fmaxf(Hz.y + b1v.y, 0.f);
    const float hz2 = fmaxf(Hz.z + b1v.z, 0.f);
    const float hz3 = fmaxf(Hz.w + b1v.w, 0.f);

    const float v0 = fmaf(hb0,wc0.x, fmaf(hb1,wc0.y, fmaf(hb2,wc0.z, hb3*wc0.w)));
    const float v1 = fmaf(hb0,wc1.x, fmaf(hb1,wc1.y, fmaf(hb2,wc1.z, hb3*wc1.w)));
    const float v2 = fmaf(hb0,wc2.x, fmaf(hb1,wc2.y, fmaf(hb2,wc2.z, hb3*wc2.w)));
    const float v3 = fmaf(hb0,wc3.x, fmaf(hb1,wc3.y, fmaf(hb2,wc3.z, hb3*wc3.w)));
    const float vx = fmaf(hx0,wc0.x, fmaf(hx1,wc0.y, fmaf(hx2,wc0.z, hx3*wc0.w)));
    const float vy = fmaf(hy0,wc0.x, fmaf(hy1,wc0.y, fmaf(hy2,wc0.z, hy3*wc0.w)));
    const float vz = fmaf(hz0,wc0.x, fmaf(hz1,wc0.y, fmaf(hz2,wc0.z, hz3*wc0.w)));

    // --- packed multi-value reduction over 16 lanes (values: v0..v3,vx,vy,vz,0)
    const bool lo1 = (lane & 1) == 0;
    float s0 = lo1 ? vx : v0;
    float s1 = lo1 ? vy : v1;
    float s2 = lo1 ? vz : v2;
    float s3 = lo1 ? 0.f : v3;
    s0 = __shfl_xor_sync(0xffffffffu, s0, 1);
    s1 = __shfl_xor_sync(0xffffffffu, s1, 1);
    s2 = __shfl_xor_sync(0xffffffffu, s2, 1);
    s3 = __shfl_xor_sync(0xffffffffu, s3, 1);
    const float a0 = (lo1 ? v0 : vx) + s0;
    const float a1 = (lo1 ? v1 : vy) + s1;
    const float a2 = (lo1 ? v2 : vz) + s2;
    const float a3 = (lo1 ? v3 : 0.f) + s3;
    const bool lo2 = ((lane >> 1) & 1) == 0;
    float u0 = lo2 ? a2 : a0;
    float u1 = lo2 ? a3 : a1;
    u0 = __shfl_xor_sync(0xffffffffu, u0, 2);
    u1 = __shfl_xor_sync(0xffffffffu, u1, 2);
    const float c0 = (lo2 ? a0 : a2) + u0;
    const float c1 = (lo2 ? a1 : a3) + u1;
    const bool lo3 = ((lane >> 2) & 1) == 0;
    float w = lo3 ? c1 : c0;
    w = __shfl_xor_sync(0xffffffffu, w, 4);
    float dsum = (lo3 ? c0 : c1) + w;
    dsum += __shfl_xor_sync(0xffffffffu, dsum, 8);
    // value j lives at half-lane L(j) = bitrev3(j): {0,4,2,6,1,5,3,7}
    const int hb16 = lane & 16;
    const float4 b2v = *reinterpret_cast<const float4*>(b2);
    const float sdf_base = __shfl_sync(0xffffffffu, dsum, hb16 + 0) + b2v.x;
    const float rgb1v    = __shfl_sync(0xffffffffu, dsum, hb16 + 4) + b2v.y;
    const float rgb2v    = __shfl_sync(0xffffffffu, dsum, hb16 + 2) + b2v.z;
    const float rgb3v    = __shfl_sync(0xffffffffu, dsum, hb16 + 6) + b2v.w;
    const float sdfx     = __shfl_sync(0xffffffffu, dsum, hb16 + 1) + b2v.x;
    const float sdfy     = __shfl_sync(0xffffffffu, dsum, hb16 + 5) + b2v.x;
    const float sdfz     = __shfl_sync(0xffffffffu, dsum, hb16 + 3) + b2v.x;

    if (sub == 0) {
        const float g0 = (sdfx - sdf_base) * 100.f;
        const float g1 = (sdfy - sdf_base) * 100.f;
        const float g2 = (sdfz - sdf_base) * 100.f;
        grad_out[point*3 + 0] = g0;
        grad_out[point*3 + 1] = g1;
        grad_out[point*3 + 2] = g2;
        const float gn  = sqrtf(g0*g0 + g1*g1 + g2*g2);
        const float inv = 1.f / (gn + 1e-8f);
        const float shifted = sdf_base + sqrtf(px*px + py*py + pz*pz) - 0.5f;
        const float xs = -shifted * 80.f;
        const float sigma = fmaxf(xs, 0.f) + log1pf(expf(-fabsf(xs)));
        const float r1 = 1.002f / (1.f + expf(-rgb1v)) - 0.001f;
        const float r2 = 1.002f / (1.f + expf(-rgb2v)) - 0.001f;
        const float r3 = 1.002f / (1.f + expf(-rgb3v)) - 0.001f;
        float4 A; A.x = r1; A.y = r2; A.z = r3; A.w = sigma;
        float4 B; B.x = g0*inv; B.y = g1*inv; B.z = g2*inv; B.w = 0.f;
        *reinterpret_cast<float4*>(&g_scr[point*8    ]) = A;
        *reinterpret_cast<float4*>(&g_scr[point*8 + 4]) = B;
    }
}

// ---------------------------------------------------------------------------
// Kernel 3: warp-per-ray compositing via multiplicative prefix scan.
// ---------------------------------------------------------------------------
__global__ void composite(float* __restrict__ out) {
    const int lane = threadIdx.x & 31;
    const int r = blockIdx.x * 8 + (threadIdx.x >> 5);

    const float tn   = g_rayp[r*2].w;
    const float span = g_rayp[r*2+1].w;
    const float delta = span * (1.0f/96.0f);

    float rgb0=0.f, rgb1=0.f, rgb2=0.f, dep=0.f, ws=0.f, n0=0.f, n1=0.f, n2=0.f;
    float Tpre = 1.f;
    #pragma unroll
    for (int k = 0; k < 3; k++) {
        const int s = k*32 + lane;
        const float4 A = *reinterpret_cast<const float4*>(&g_scr[(size_t)(r*SPR + s)*8]);
        const float4 B = *reinterpret_cast<const float4*>(&g_scr[(size_t)(r*SPR + s)*8 + 4]);
        const float e = expf(-A.w * delta);
        const float m = e + 1e-10f;
        const float alpha = 1.f - e;
        float incl = m;
        #pragma unroll
        for (int off = 1; off < 32; off <<= 1) {
            float t = __shfl_up_sync(0xffffffffu, incl, off);
            if (lane >= off) incl *= t;
        }
        float excl = __shfl_up_sync(0xffffffffu, incl, 1);
        if (lane == 0) excl = 1.f;
        const float tot = __shfl_sync(0xffffffffu, incl, 31);
        const float T = Tpre * excl;
        const float w = alpha * T;
        rgb0 = fmaf(w, A.x, rgb0);
        rgb1 = fmaf(w, A.y, rgb1);
        rgb2 = fmaf(w, A.z, rgb2);
        dep  = fmaf(w, tn + span * (((float)s + 0.5f) * (1.0f/96.0f)), dep);
        ws  += w;
        n0 = fmaf(w, B.x, n0);
        n1 = fmaf(w, B.y, n1);
        n2 = fmaf(w, B.z, n2);
        Tpre *= tot;
    }
    rgb0 = sum32(rgb0);
    rgb1 = sum32(rgb1);
    rgb2 = sum32(rgb2);
    dep  = sum32(dep);
    ws   = sum32(ws);
    n0   = sum32(n0);
    n1   = sum32(n1);
    n2   = sum32(n2);

    if (lane == 0) {
        const float bg = 1.f - ws;
        const float nn  = sqrtf(n0*n0 + n1*n1 + n2*n2);
        const float inv = 1.f / (nn + 1e-8f);
        out[r]         = rgb0 + bg;
        out[ 4096 + r] = rgb1 + bg;
        out[ 8192 + r] = rgb2 + bg;
        out[12288 + r] = dep;
        out[16384 + r] = ws;
        out[20480 + r] = ((n0*inv) + 1.f) * 0.5f * ws;
        out[24576 + r] = ((n1*inv) + 1.f) * 0.5f * ws;
        out[28672 + r] = ((n2*inv) + 1.f) * 0.5f * ws;
    }
}

// ---------------------------------------------------------------------------
extern "C" void kernel_launch(void* const* d_in, const int* in_sizes, int n_in,
                              void* d_out, int out_size) {
    const float* planes = (const float*)d_in[0];
    const float* ro     = (const float*)d_in[1];
    const float* rd     = (const float*)d_in[2];
    const float* W1     = (const float*)d_in[3];
    const float* b1     = (const float*)d_in[4];
    const float* W2     = (const float*)d_in[5];
    const float* b2     = (const float*)d_in[6];
    float* out = (float*)d_out;

    setup_kernel<<<(3*PLANE_TEXELS*16 + 255)/256, 256>>>(W2, ro, rd);
    project_planes<<<3*GRIDW, 512>>>(planes, W1);
    point_kernel<<<NPTS/16, 256>>>(b1, b2, out + 32768);
    composite<<<NRAY/8, 256>>>(out);
}